// round 10
// baseline (speedup 1.0000x reference)
#include <cuda_runtime.h>
#include <cuda_fp16.h>
#include <cstdint>

#define C 128
#define N_MAX 16384
#define E_MAX 1100000
#define CAP 256

// Static scratch (no allocs allowed)
__device__ int g_idx64;
__device__ int g_cnt[N_MAX];
__device__ int g_ssrc[N_MAX * CAP];           // bucketed src ids
__device__ int g_ovf_cnt;
__device__ long long g_ovf[E_MAX];            // overflow edges (dst<<32 | src)
__device__ __half g_xh[N_MAX * C];            // fp16 copy of x for gather stream

__global__ void detect_idx_kernel(const void* __restrict__ ei, int n_nodes) {
    if (threadIdx.x == 0 && blockIdx.x == 0) {
        const long long* p = (const long long*)ei;
        int ok = 1;
        #pragma unroll
        for (int i = 0; i < 16; i++) {
            long long v = p[i];
            if (v < 0 || v >= (long long)n_nodes) { ok = 0; }
        }
        g_idx64 = ok;
    }
}

// Merged prep: fp32->fp16 convert of x, then bucket edges by destination.
__global__ void prep_kernel(const float* __restrict__ x,
                            const void* __restrict__ ei,
                            int n_edges, int n_nodes, int n_f4) {
    __shared__ int s_idx64;
    if (threadIdx.x == 0) {
        const long long* p = (const long long*)ei;
        int ok = 1;
        #pragma unroll
        for (int i = 0; i < 16; i++) {
            long long v = p[i];
            if (v < 0 || v >= (long long)n_nodes) { ok = 0; }
        }
        s_idx64 = ok;
    }

    int gid = blockIdx.x * blockDim.x + threadIdx.x;
    int stride = gridDim.x * blockDim.x;

    // ---- convert loop ----
    for (int i = gid; i < n_f4; i += stride) {
        float4 v = __ldg((const float4*)x + i);
        __half2 h0 = __floats2half2_rn(v.x, v.y);
        __half2 h1 = __floats2half2_rn(v.z, v.w);
        uint2 u;
        u.x = *reinterpret_cast<unsigned*>(&h0);
        u.y = *reinterpret_cast<unsigned*>(&h1);
        ((uint2*)g_xh)[i] = u;
    }

    __syncthreads();
    const int idx64 = s_idx64;

    // ---- bucket loop ----
    const long long* p64 = (const long long*)ei;
    const int*       p32 = (const int*)ei;
    for (int e = gid; e < n_edges; e += stride) {
        int s, d;
        if (idx64) {
            s = (int)__ldg(p64 + e);
            d = (int)__ldg(p64 + n_edges + e);
        } else {
            s = __ldg(p32 + e);
            d = __ldg(p32 + n_edges + e);
        }
        int pos = atomicAdd(&g_cnt[d], 1);
        if (pos < CAP) {
            g_ssrc[d * CAP + pos] = s;
        } else {
            int o = atomicAdd(&g_ovf_cnt, 1);
            g_ovf[o] = ((long long)d << 32) | (unsigned)s;
        }
    }
}

// One warp per destination node; warp = 4 groups of 8 lanes, 4 edges/iter.
// Lane (grp g, sub t) owns channels [16t, 16t+16). Src rows read as fp16.
__global__ __launch_bounds__(256) void gather_kernel(
    const float* __restrict__ x,
    const float* __restrict__ W2,
    const float* __restrict__ W3,
    float* __restrict__ out,
    int n_nodes)
{
    const int lane = threadIdx.x & 31;
    const int t = lane & 7;
    const int grp = lane >> 3;
    const int j = (int)((blockIdx.x * (unsigned)blockDim.x + threadIdx.x) >> 5);
    if (j >= n_nodes) return;

    // w3xj for my 16 channels
    float wxf[16];
    #pragma unroll
    for (int m = 0; m < 4; m++) {
        float4 xj = __ldg((const float4*)(x + (long long)j * C) + (t * 4 + m));
        float4 w3 = __ldg((const float4*)W3 + (t * 4 + m));
        wxf[4 * m + 0] = w3.x * xj.x;
        wxf[4 * m + 1] = w3.y * xj.y;
        wxf[4 * m + 2] = w3.z * xj.z;
        wxf[4 * m + 3] = w3.w * xj.w;
    }

    float acc[16];
    #pragma unroll
    for (int k = 0; k < 16; k++) acc[k] = 0.f;

    const int deg_raw = __ldg(&g_cnt[j]);
    const int deg = (deg_raw > CAP) ? CAP : deg_raw;
    const int* bucket = &g_ssrc[j * CAP];

    for (int i = 0; i < deg; i += 4) {
        int e = i + grp;
        bool v = (e < deg);
        int s = __ldg(bucket + (v ? e : i));   // broadcast within group

        const uint4* row = (const uint4*)(g_xh + (long long)s * C);
        uint4 ua = __ldg(row + 2 * t);
        uint4 ub = __ldg(row + 2 * t + 1);

        float2 f[8];
        f[0] = __half22float2(*(__half2*)&ua.x);
        f[1] = __half22float2(*(__half2*)&ua.y);
        f[2] = __half22float2(*(__half2*)&ua.z);
        f[3] = __half22float2(*(__half2*)&ua.w);
        f[4] = __half22float2(*(__half2*)&ub.x);
        f[5] = __half22float2(*(__half2*)&ub.y);
        f[6] = __half22float2(*(__half2*)&ub.z);
        f[7] = __half22float2(*(__half2*)&ub.w);

        float p = 0.f;
        #pragma unroll
        for (int m = 0; m < 8; m++)
            p += f[m].x * wxf[2 * m] + f[m].y * wxf[2 * m + 1];

        // reduce across the 8-lane group (4 groups concurrently)
        p += __shfl_xor_sync(0xffffffffu, p, 1);
        p += __shfl_xor_sync(0xffffffffu, p, 2);
        p += __shfl_xor_sync(0xffffffffu, p, 4);

        if (v) {
            #pragma unroll
            for (int m = 0; m < 8; m++) {
                acc[2 * m]     += p * f[m].x;
                acc[2 * m + 1] += p * f[m].y;
            }
        }
    }

    // Rare path: this node overflowed CAP — pick up its overflow edges.
    if (deg_raw > CAP) {
        int n = g_ovf_cnt;
        for (int e2 = 0; e2 < n; e2++) {
            long long pk = g_ovf[e2];
            if ((int)(pk >> 32) != j) continue;
            int s = (int)(unsigned)(pk & 0xffffffffLL);
            const uint4* row = (const uint4*)(g_xh + (long long)s * C);
            uint4 ua = __ldg(row + 2 * t);
            uint4 ub = __ldg(row + 2 * t + 1);
            float2 f[8];
            f[0] = __half22float2(*(__half2*)&ua.x);
            f[1] = __half22float2(*(__half2*)&ua.y);
            f[2] = __half22float2(*(__half2*)&ua.z);
            f[3] = __half22float2(*(__half2*)&ua.w);
            f[4] = __half22float2(*(__half2*)&ub.x);
            f[5] = __half22float2(*(__half2*)&ub.y);
            f[6] = __half22float2(*(__half2*)&ub.z);
            f[7] = __half22float2(*(__half2*)&ub.w);
            float p = 0.f;
            #pragma unroll
            for (int m = 0; m < 8; m++)
                p += f[m].x * wxf[2 * m] + f[m].y * wxf[2 * m + 1];
            p += __shfl_xor_sync(0xffffffffu, p, 1);
            p += __shfl_xor_sync(0xffffffffu, p, 2);
            p += __shfl_xor_sync(0xffffffffu, p, 4);
            if (grp == 0) {           // all groups computed the same edge
                #pragma unroll
                for (int m = 0; m < 8; m++) {
                    acc[2 * m]     += p * f[m].x;
                    acc[2 * m + 1] += p * f[m].y;
                }
            }
        }
    }

    // Cross-group combine (lanes with equal t share channels)
    #pragma unroll
    for (int k = 0; k < 16; k++) {
        acc[k] += __shfl_xor_sync(0xffffffffu, acc[k], 8);
        acc[k] += __shfl_xor_sync(0xffffffffu, acc[k], 16);
    }

    if (grp == 0) {
        float4* orow = (float4*)(out + (long long)j * C);
        #pragma unroll
        for (int m = 0; m < 4; m++) {
            float4 w2 = __ldg((const float4*)W2 + (t * 4 + m));
            float4 r;
            r.x = acc[4 * m + 0] * w2.x;
            r.y = acc[4 * m + 1] * w2.y;
            r.z = acc[4 * m + 2] * w2.z;
            r.w = acc[4 * m + 3] * w2.w;
            orow[t * 4 + m] = r;
        }
    }
}

// ---------------- Fallback (R5 kernel) for unexpected shapes ----------------
__global__ __launch_bounds__(256, 4) void edge_scatter_kernel(
    const float* __restrict__ x, const void* __restrict__ ei,
    const float* __restrict__ W2, const float* __restrict__ W3,
    float* __restrict__ out, int n_edges)
{
    const int lane = threadIdx.x & 31;
    const int t = lane & 7;
    const int grp = lane >> 3;
    const int warp_id = (int)((blockIdx.x * (unsigned)blockDim.x + threadIdx.x) >> 5);
    const int n_warps = (int)((gridDim.x * (unsigned)blockDim.x) >> 5);

    float4 w2v[4], w3v[4];
    #pragma unroll
    for (int k = 0; k < 4; k++) {
        w3v[k] = __ldg((const float4*)W3 + (t + 8 * k));
        w2v[k] = __ldg((const float4*)W2 + (t + 8 * k));
    }
    const int idx64 = g_idx64;
    const long long* p64 = (const long long*)ei;
    const int*       p32 = (const int*)ei;

    for (int base = warp_id * 4; base < n_edges; base += n_warps * 4) {
        int e = base + grp;
        bool valid = (e < n_edges);
        int ec = valid ? e : (n_edges - 1);
        long long src, dst;
        if (idx64) { src = __ldg(p64 + ec); dst = __ldg(p64 + n_edges + ec); }
        else { src = (long long)__ldg(p32 + ec); dst = (long long)__ldg(p32 + n_edges + ec); }

        const float4* srow = (const float4*)(x + src * C);
        const float4* drow = (const float4*)(x + dst * C);
        float4 vs[4], vd[4];
        #pragma unroll
        for (int k = 0; k < 4; k++) vs[k] = __ldg(srow + (t + 8 * k));
        #pragma unroll
        for (int k = 0; k < 4; k++) vd[k] = __ldg(drow + (t + 8 * k));

        float part = 0.f;
        #pragma unroll
        for (int k = 0; k < 4; k++)
            part += vs[k].x * w3v[k].x * vd[k].x + vs[k].y * w3v[k].y * vd[k].y
                  + vs[k].z * w3v[k].z * vd[k].z + vs[k].w * w3v[k].w * vd[k].w;
        part += __shfl_xor_sync(0xffffffffu, part, 4);
        part += __shfl_xor_sync(0xffffffffu, part, 2);
        part += __shfl_xor_sync(0xffffffffu, part, 1);

        if (valid) {
            float* op = out + dst * C;
            #pragma unroll
            for (int k = 0; k < 4; k++) {
                float4 r;
                r.x = part * vs[k].x * w2v[k].x; r.y = part * vs[k].y * w2v[k].y;
                r.z = part * vs[k].z * w2v[k].z; r.w = part * vs[k].w * w2v[k].w;
                asm volatile("red.global.add.v4.f32 [%0], {%1,%2,%3,%4};"
                             :: "l"(op + (t + 8 * k) * 4),
                                "f"(r.x), "f"(r.y), "f"(r.z), "f"(r.w) : "memory");
            }
        }
    }
}

extern "C" void kernel_launch(void* const* d_in, const int* in_sizes, int n_in,
                              void* d_out, int out_size) {
    const float* x  = (const float*)d_in[0];
    const void*  ei = d_in[1];
    const float* W2 = (const float*)d_in[2];
    const float* W3 = (const float*)d_in[3];
    float* out = (float*)d_out;

    int n_nodes = in_sizes[0] / C;
    int n_edges = in_sizes[1] / 2;

    if (n_nodes <= N_MAX && n_edges <= E_MAX) {
        void* cnt_ptr = nullptr;
        void* ovf_ptr = nullptr;
        cudaGetSymbolAddress(&cnt_ptr, g_cnt);
        cudaGetSymbolAddress(&ovf_ptr, g_ovf_cnt);
        cudaMemsetAsync(cnt_ptr, 0, (size_t)n_nodes * sizeof(int), 0);
        cudaMemsetAsync(ovf_ptr, 0, sizeof(int), 0);

        int n_f4 = n_nodes * (C / 4);
        prep_kernel<<<512, 256>>>(x, ei, n_edges, n_nodes, n_f4);

        int warps_per_block = 256 / 32;
        int blocks = (n_nodes + warps_per_block - 1) / warps_per_block;
        gather_kernel<<<blocks, 256>>>(x, W2, W3, out, n_nodes);
    } else {
        detect_idx_kernel<<<1, 32>>>(ei, n_nodes);
        cudaMemsetAsync(out, 0, (size_t)out_size * sizeof(float), 0);
        edge_scatter_kernel<<<2048, 256>>>(x, ei, W2, W3, out, n_edges);
    }
}